// round 3
// baseline (speedup 1.0000x reference)
#include <cuda_runtime.h>
#include <cstdint>

#define N_NODES 50000
#define N_EDGES 800000
#define E_TOT   (N_EDGES + N_NODES)
#define IN_F    129

// ---------------- scratch (static device globals; no allocation APIs) ----------------
__device__ __align__(16) float g_h1  [N_NODES * 128];
__device__ __align__(16) float g_out1[N_NODES * 128];
__device__ __align__(16) float g_h2  [N_NODES * 160];
__device__ __align__(16) float g_as1 [N_NODES * 4];
__device__ __align__(16) float g_ad1 [N_NODES * 4];
__device__ __align__(16) float g_as2 [N_NODES * 4];
__device__ __align__(16) float g_ad2 [N_NODES * 4];
__device__ __align__(16) float g_W1s [IN_F * 128];
__device__ __align__(16) float g_b1c [128];
__device__ int   g_deg [N_NODES];
__device__ int   g_cnt [N_NODES];
__device__ int   g_rowp[N_NODES + 1];
__device__ int   g_colv[E_TOT];
__device__ int   g_is64;

// ---------------- edge_index dtype sniff ----------------
// int64 little-endian with values < 2^31  =>  every odd 32-bit word is 0.
// Genuine int32 random edges: odd words are edge values (nonzero w.h.p.).
__global__ void detect_kernel(const int* __restrict__ ei32) {
    int ok = 1;
    for (int i = 1; i < 256; i += 2)
        if (ei32[i] != 0) ok = 0;
    g_is64 = ok;
}

__device__ __forceinline__ int edge_at(const void* ei, long long idx) {
    int v;
    if (g_is64) v = (int)((const long long*)ei)[idx];
    else        v = ((const int*)ei)[idx];
    // clamp defensively: identity for valid input, prevents wild addresses otherwise
    v = v < 0 ? 0 : v;
    return v >= N_NODES ? N_NODES - 1 : v;
}

// ---------------- fold BatchNorm into W1 ----------------
// BN(x)@W1 == x @ (diag(scale)W1) + (shift@W1 + b1),  scale=gamma*rsqrt(var+eps)
__global__ void prep_w1_kernel(const float* __restrict__ W1,
                               const float* __restrict__ gamma,
                               const float* __restrict__ beta,
                               const float* __restrict__ mean,
                               const float* __restrict__ var,
                               const float* __restrict__ b1) {
    int c = threadIdx.x;           // 128 threads
    float acc = b1[c];
    for (int k = 0; k < IN_F; ++k) {
        float sc = gamma[k] * rsqrtf(var[k] + 1e-5f);
        float sh = beta[k] - mean[k] * sc;
        float w  = W1[k * 128 + c];
        g_W1s[k * 128 + c] = sc * w;
        acc += sh * w;
    }
    g_b1c[c] = acc;
}

// ---------------- CSR build (by destination) ----------------
__global__ void zero_kernel() {
    int i = blockIdx.x * blockDim.x + threadIdx.x;
    if (i < N_NODES) { g_deg[i] = 0; g_cnt[i] = 0; }
}

__global__ void count_kernel(const void* __restrict__ ei) {
    int e = blockIdx.x * blockDim.x + threadIdx.x;
    if (e >= E_TOT) return;
    int dst = (e < N_EDGES) ? edge_at(ei, (long long)N_EDGES + e) : (e - N_EDGES);
    atomicAdd(&g_deg[dst], 1);
}

__global__ void scan_kernel() {     // single block, 1024 threads
    __shared__ int sums[1024];
    int t = threadIdx.x;
    const int ITEMS = (N_NODES + 1023) / 1024;
    int start = t * ITEMS;
    int end   = min(start + ITEMS, N_NODES);
    int mySum = 0;
    for (int i = start; i < end; ++i) mySum += g_deg[i];
    sums[t] = mySum;
    __syncthreads();
    for (int off = 1; off < 1024; off <<= 1) {
        int v = (t >= off) ? sums[t - off] : 0;
        __syncthreads();
        sums[t] += v;
        __syncthreads();
    }
    int run = sums[t] - mySum;      // exclusive prefix of my chunk
    for (int i = start; i < end; ++i) { g_rowp[i] = run; run += g_deg[i]; }
    if (t == 1023) g_rowp[N_NODES] = sums[1023];
}

__global__ void scatter_kernel(const void* __restrict__ ei) {
    int e = blockIdx.x * blockDim.x + threadIdx.x;
    if (e >= E_TOT) return;
    int src, dst;
    if (e < N_EDGES) {
        src = edge_at(ei, e);
        dst = edge_at(ei, (long long)N_EDGES + e);
    } else {
        src = dst = e - N_EDGES;
    }
    int pos = g_rowp[dst] + atomicAdd(&g_cnt[dst], 1);
    if (pos < E_TOT) g_colv[pos] = src;
}

// ---------------- tiled fp32 GEMM ----------------
// LAYER==1: g_h1 [M,128] = A(param x)[M,129] @ g_W1s + g_b1c
// LAYER==2: g_h2 [M,160] = g_out1[M,128] @ B(param W2)
template<int TN, int LAYER>
__global__ void gemm_kernel(const float* __restrict__ Ap,
                            const float* __restrict__ Bp, int M, int K) {
    constexpr int NC = 16 * TN;
    constexpr int BM = 64, BK = 16;
    const float* A = (LAYER == 1) ? Ap : g_out1;
    const float* B = (LAYER == 1) ? g_W1s : Bp;
    float*       C = (LAYER == 1) ? g_h1 : g_h2;
    const int lda  = (LAYER == 1) ? IN_F : 128;

    __shared__ float As[BM][BK + 1];
    __shared__ float Bs[BK][NC];
    int tid = threadIdx.x;
    int tx = tid & 15;          // col group
    int ty = tid >> 4;          // row group (0..15), 4 rows each
    int rowBase = blockIdx.x * BM;

    float acc[4][TN];
#pragma unroll
    for (int i = 0; i < 4; ++i)
#pragma unroll
        for (int j = 0; j < TN; ++j) acc[i][j] = 0.f;

    for (int k0 = 0; k0 < K; k0 += BK) {
#pragma unroll
        for (int i = 0; i < (BM * BK) / 256; ++i) {
            int idx = tid + i * 256;
            int r = idx >> 4, kk = idx & 15;
            int gr = rowBase + r, gk = k0 + kk;
            As[r][kk] = (gr < M && gk < K) ? A[(size_t)gr * lda + gk] : 0.f;
        }
#pragma unroll
        for (int i = 0; i < (BK * NC) / 256; ++i) {
            int idx = tid + i * 256;
            int kk = idx / NC, c = idx % NC;
            int gk = k0 + kk;
            Bs[kk][c] = (gk < K) ? B[gk * NC + c] : 0.f;
        }
        __syncthreads();
#pragma unroll
        for (int kk = 0; kk < BK; ++kk) {
            float a[4], b[TN];
#pragma unroll
            for (int i = 0; i < 4; ++i) a[i] = As[ty * 4 + i][kk];
#pragma unroll
            for (int j = 0; j < TN; ++j) b[j] = Bs[kk][tx * TN + j];
#pragma unroll
            for (int i = 0; i < 4; ++i)
#pragma unroll
                for (int j = 0; j < TN; ++j)
                    acc[i][j] = fmaf(a[i], b[j], acc[i][j]);
        }
        __syncthreads();
    }
#pragma unroll
    for (int i = 0; i < 4; ++i) {
        int gr = rowBase + ty * 4 + i;
        if (gr < M) {
#pragma unroll
            for (int j = 0; j < TN; ++j) {
                int c = tx * TN + j;
                float v = acc[i][j];
                if (LAYER == 1) v += g_b1c[c];
                C[(size_t)gr * NC + c] = v;
            }
        }
    }
}

// ---------------- per-node attention coefficients ----------------
// one warp per node; lane owns channels c = lane*NJ+j (all in head lane>>3)
template<int NJ, int LAYER>
__global__ void alpha_kernel(const float* __restrict__ a_src,
                             const float* __restrict__ a_dst, int n) {
    constexpr int NC = 32 * NJ;
    const float* h  = (LAYER == 1) ? g_h1  : g_h2;
    float* out_s    = (LAYER == 1) ? g_as1 : g_as2;
    float* out_d    = (LAYER == 1) ? g_ad1 : g_ad2;
    int gw   = (blockIdx.x * blockDim.x + threadIdx.x) >> 5;
    int lane = threadIdx.x & 31;
    if (gw >= n) return;
    const float* hp = h + (size_t)gw * NC + lane * NJ;
    float ss = 0.f, sd = 0.f;
#pragma unroll
    for (int j = 0; j < NJ; ++j) {
        float v = hp[j];
        int c = lane * NJ + j;
        ss = fmaf(v, a_src[c], ss);
        sd = fmaf(v, a_dst[c], sd);
    }
    // reduce within 8-lane head groups
#pragma unroll
    for (int off = 4; off; off >>= 1) {
        ss += __shfl_down_sync(0xffffffffu, ss, off, 8);
        sd += __shfl_down_sync(0xffffffffu, sd, off, 8);
    }
    if ((lane & 7) == 0) {
        out_s[gw * 4 + (lane >> 3)] = ss;
        out_d[gw * 4 + (lane >> 3)] = sd;
    }
}

// ---------------- fused edge pass: online segment-softmax + weighted gather ----------------
// One warp per dst node. Lane (lane&3) tracks softmax state of that head;
// lane's output channels c = lane*NJ+j all belong to head (lane>>3).
template<int NJ, int LAYER>
__global__ void agg_kernel(const float* __restrict__ bias,
                           float* __restrict__ outp, int n) {
    constexpr int NC = 32 * NJ;
    const float* h   = (LAYER == 1) ? g_h1  : g_h2;
    const float* asv = (LAYER == 1) ? g_as1 : g_as2;
    const float* adv = (LAYER == 1) ? g_ad1 : g_ad2;
    float* out       = (LAYER == 1) ? g_out1 : outp;
    int gw   = (blockIdx.x * blockDim.x + threadIdx.x) >> 5;
    int lane = threadIdx.x & 31;
    if (gw >= n) return;
    int myh  = lane & 3;    // head whose softmax state this lane tracks
    int hidx = lane >> 3;   // head owning this lane's channels

    float4 adq = *reinterpret_cast<const float4*>(adv + gw * 4);
    float ad_m = (myh == 0) ? adq.x : (myh == 1) ? adq.y : (myh == 2) ? adq.z : adq.w;

    float m = -1e30f, s = 0.f;
    float acc[NJ];
#pragma unroll
    for (int j = 0; j < NJ; ++j) acc[j] = 0.f;

    int e0 = g_rowp[gw], e1 = g_rowp[gw + 1];
    for (int k = e0; k < e1; ++k) {
        int src = g_colv[k];
        float4 aq = *reinterpret_cast<const float4*>(asv + src * 4);
        float av = (myh == 0) ? aq.x : (myh == 1) ? aq.y : (myh == 2) ? aq.z : aq.w;
        float e = av + ad_m;
        e = fmaxf(e, 0.2f * e);                 // LeakyReLU
        float nm = fmaxf(m, e);
        float fl = __expf(m - nm);
        float pl = __expf(e - nm);
        s = fmaf(s, fl, pl);
        m = nm;
        float fj = __shfl_sync(0xffffffffu, fl, hidx);
        float pj = __shfl_sync(0xffffffffu, pl, hidx);
        const float* hp = h + (size_t)src * NC + lane * NJ;
        if (NJ == 4) {
            float4 hv = *reinterpret_cast<const float4*>(hp);
            acc[0] = fmaf(pj, hv.x, acc[0] * fj);
            acc[1] = fmaf(pj, hv.y, acc[1] * fj);
            acc[2] = fmaf(pj, hv.z, acc[2] * fj);
            acc[3] = fmaf(pj, hv.w, acc[3] * fj);
        } else {
#pragma unroll
            for (int j = 0; j < NJ; ++j)
                acc[j] = fmaf(pj, hp[j], acc[j] * fj);
        }
    }
    float sj  = __shfl_sync(0xffffffffu, s, hidx);
    float inv = 1.0f / sj;
    float* op = out + (size_t)gw * NC + lane * NJ;
#pragma unroll
    for (int j = 0; j < NJ; ++j) {
        float v = acc[j] * inv + bias[lane * NJ + j];
        if (LAYER == 1) v = (v > 0.f) ? v : expm1f(v);   // ELU after layer 1
        op[j] = v;
    }
}

// ---------------- launch ----------------
extern "C" void kernel_launch(void* const* d_in, const int* in_sizes, int n_in,
                              void* d_out, int out_size) {
    const float* x      = (const float*)d_in[0];
    const void*  ei     = d_in[1];                 // int32 or int64 — sniffed on device
    const float* gamma  = (const float*)d_in[2];
    const float* beta   = (const float*)d_in[3];
    const float* mean   = (const float*)d_in[4];
    const float* var    = (const float*)d_in[5];
    const float* W1     = (const float*)d_in[6];
    const float* a1_src = (const float*)d_in[7];
    const float* a1_dst = (const float*)d_in[8];
    const float* b1     = (const float*)d_in[9];
    const float* W2     = (const float*)d_in[10];
    const float* a2_src = (const float*)d_in[11];
    const float* a2_dst = (const float*)d_in[12];
    const float* b2     = (const float*)d_in[13];
    float*       out    = (float*)d_out;

    const int NWB = 6250;                 // warp-per-node kernels: 256 thr = 8 nodes/block
    const int EB  = (E_TOT + 255) / 256;

    // CSR build
    detect_kernel<<<1, 1>>>((const int*)ei);
    zero_kernel<<<(N_NODES + 255) / 256, 256>>>();
    count_kernel<<<EB, 256>>>(ei);
    scan_kernel<<<1, 1024>>>();
    scatter_kernel<<<EB, 256>>>(ei);

    // BN fold + layer 1
    prep_w1_kernel<<<1, 128>>>(W1, gamma, beta, mean, var, b1);
    gemm_kernel<8, 1><<<(N_NODES + 63) / 64, 256>>>(x, nullptr, N_NODES, IN_F);
    alpha_kernel<4, 1><<<NWB, 256>>>(a1_src, a1_dst, N_NODES);
    agg_kernel<4, 1><<<NWB, 256>>>(b1, nullptr, N_NODES);

    // layer 2
    gemm_kernel<10, 2><<<(N_NODES + 63) / 64, 256>>>(nullptr, W2, N_NODES, 128);
    alpha_kernel<5, 2><<<NWB, 256>>>(a2_src, a2_dst, N_NODES);
    agg_kernel<5, 2><<<NWB, 256>>>(b2, out, N_NODES);
}

// round 4
// speedup vs baseline: 1.3287x; 1.3287x over previous
#include <cuda_runtime.h>
#include <cstdint>

#define N_NODES 50000
#define N_EDGES 800000
#define E_TOT   (N_EDGES + N_NODES)
#define IN_F    129
#define SCAN_B  ((N_NODES + 255) / 256)   // 196

// ---------------- scratch (static device globals; no allocation APIs) ----------------
__device__ __align__(16) float g_h1  [N_NODES * 128];
__device__ __align__(16) float g_out1[N_NODES * 128];
__device__ __align__(16) float g_h2  [N_NODES * 160];
__device__ __align__(16) float g_as1 [N_NODES * 4];
__device__ __align__(16) float g_ad1 [N_NODES * 4];
__device__ __align__(16) float g_as2 [N_NODES * 4];
__device__ __align__(16) float g_ad2 [N_NODES * 4];
__device__ __align__(16) float g_W1s [IN_F * 128];
__device__ __align__(16) float g_b1c [128];
__device__ int   g_deg [N_NODES];
__device__ int   g_cnt [N_NODES];
__device__ int   g_rowp[N_NODES + 1];
__device__ int   g_colv[E_TOT];
__device__ int   g_bsum[256];
__device__ int   g_is64;

// ---------------- edge_index dtype sniff ----------------
__global__ void detect_kernel(const int* __restrict__ ei32) {
    int ok = 1;
    for (int i = 1; i < 256; i += 2)
        if (ei32[i] != 0) ok = 0;
    g_is64 = ok;
}

__device__ __forceinline__ int edge_at(const void* ei, long long idx) {
    int v;
    if (g_is64) v = (int)((const long long*)ei)[idx];
    else        v = ((const int*)ei)[idx];
    v = v < 0 ? 0 : v;
    return v >= N_NODES ? N_NODES - 1 : v;
}

// ---------------- fold BatchNorm into W1 ----------------
__global__ void prep_w1_kernel(const float* __restrict__ W1,
                               const float* __restrict__ gamma,
                               const float* __restrict__ beta,
                               const float* __restrict__ mean,
                               const float* __restrict__ var,
                               const float* __restrict__ b1) {
    int c = threadIdx.x;           // 128 threads
    float acc = b1[c];
    for (int k = 0; k < IN_F; ++k) {
        float sc = gamma[k] * rsqrtf(var[k] + 1e-5f);
        float sh = beta[k] - mean[k] * sc;
        float w  = W1[k * 128 + c];
        g_W1s[k * 128 + c] = sc * w;
        acc += sh * w;
    }
    g_b1c[c] = acc;
}

// ---------------- CSR build (by destination) ----------------
__global__ void zero_kernel() {
    int i = blockIdx.x * blockDim.x + threadIdx.x;
    if (i < N_NODES) { g_deg[i] = 0; g_cnt[i] = 0; }
}

__global__ void count_kernel(const void* __restrict__ ei) {
    int e = blockIdx.x * blockDim.x + threadIdx.x;
    if (e >= E_TOT) return;
    int dst = (e < N_EDGES) ? edge_at(ei, (long long)N_EDGES + e) : (e - N_EDGES);
    atomicAdd(&g_deg[dst], 1);
}

// 3-phase scan: block sums -> scan sums -> block-local scan + offset
__global__ void scan1_kernel() {                 // SCAN_B blocks x 256
    __shared__ int w[8];
    int i = blockIdx.x * 256 + threadIdx.x;
    int v = (i < N_NODES) ? g_deg[i] : 0;
#pragma unroll
    for (int off = 16; off; off >>= 1) v += __shfl_down_sync(0xffffffffu, v, off);
    if ((threadIdx.x & 31) == 0) w[threadIdx.x >> 5] = v;
    __syncthreads();
    if (threadIdx.x == 0) {
        int s = 0;
#pragma unroll
        for (int j = 0; j < 8; ++j) s += w[j];
        g_bsum[blockIdx.x] = s;
    }
}

__global__ void scan2_kernel() {                 // 1 block x 256
    __shared__ int sh[256];
    int t = threadIdx.x;
    int v = (t < SCAN_B) ? g_bsum[t] : 0;
    sh[t] = v;
    __syncthreads();
    for (int off = 1; off < 256; off <<= 1) {
        int u = (t >= off) ? sh[t - off] : 0;
        __syncthreads();
        sh[t] += u;
        __syncthreads();
    }
    if (t < SCAN_B) g_bsum[t] = sh[t] - v;       // exclusive block offset
    if (t == 0) g_rowp[N_NODES] = E_TOT;
}

__global__ void scan3_kernel() {                 // SCAN_B blocks x 256
    __shared__ int wsum[8];
    int t = threadIdx.x, lane = t & 31, w = t >> 5;
    int i = blockIdx.x * 256 + t;
    int v = (i < N_NODES) ? g_deg[i] : 0;
    int inc = v;
#pragma unroll
    for (int off = 1; off < 32; off <<= 1) {
        int u = __shfl_up_sync(0xffffffffu, inc, off);
        if (lane >= off) inc += u;
    }
    if (lane == 31) wsum[w] = inc;
    __syncthreads();
    if (t == 0) {
        int r = 0;
#pragma unroll
        for (int j = 0; j < 8; ++j) { int x = wsum[j]; wsum[j] = r; r += x; }
    }
    __syncthreads();
    if (i < N_NODES) g_rowp[i] = g_bsum[blockIdx.x] + wsum[w] + inc - v;
}

__global__ void scatter_kernel(const void* __restrict__ ei) {
    int e = blockIdx.x * blockDim.x + threadIdx.x;
    if (e >= E_TOT) return;
    int src, dst;
    if (e < N_EDGES) {
        src = edge_at(ei, e);
        dst = edge_at(ei, (long long)N_EDGES + e);
    } else {
        src = dst = e - N_EDGES;
    }
    int pos = g_rowp[dst] + atomicAdd(&g_cnt[dst], 1);
    if (pos < E_TOT) g_colv[pos] = src;
}

// ---------------- TF32 tensor-core GEMM ----------------
// LAYER==1: g_h1 [M,128] = x[M,129] @ g_W1s + g_b1c
// LAYER==2: g_h2 [M,160] = g_out1[M,128] @ W2
// Block: 256 thr (8 warps), tile BM=128 x full NC, BK=32. Warp w: rows w*16..+15.
__device__ __forceinline__ uint32_t f2tf32(float v) {
    uint32_t r;
    asm("cvt.rna.tf32.f32 %0, %1;" : "=r"(r) : "f"(v));
    return r;
}

template<int LAYER>
__global__ __launch_bounds__(256) void gemm_tc_kernel(const float* __restrict__ Ap,
                                                      const float* __restrict__ Bp,
                                                      int M) {
    constexpr int NC  = (LAYER == 1) ? 128 : 160;
    constexpr int K   = (LAYER == 1) ? IN_F : 128;
    constexpr int LDA = (LAYER == 1) ? IN_F : 128;
    constexpr int BK  = 32;
    constexpr int NT  = NC / 8;                 // mma tiles in N
    const float* A = (LAYER == 1) ? Ap    : g_out1;
    const float* B = (LAYER == 1) ? g_W1s : Bp;
    float*       C = (LAYER == 1) ? g_h1  : g_h2;

    __shared__ uint32_t As[128][BK + 4];        // +4: conflict-free frag loads
    __shared__ uint32_t Bs[BK][NC + 8];         // +8: conflict-free frag loads

    int tid  = threadIdx.x;
    int lane = tid & 31;
    int m0   = (tid >> 5) * 16;                 // warp's row offset in tile
    int qr   = lane >> 2, qc = lane & 3;
    int rowBase = blockIdx.x * 128;

    float acc[NT][4];
#pragma unroll
    for (int nt = 0; nt < NT; ++nt)
#pragma unroll
        for (int j = 0; j < 4; ++j) acc[nt][j] = 0.f;

    for (int k0 = 0; k0 < K; k0 += BK) {
        // fill As (128x32): 16 elems/thread, coalesced over k
#pragma unroll
        for (int i = 0; i < 16; ++i) {
            int idx = tid + i * 256;
            int r = idx >> 5, kk = idx & 31;
            int gr = rowBase + r, gk = k0 + kk;
            float v = (gr < M && gk < K) ? A[(size_t)gr * LDA + gk] : 0.f;
            As[r][kk] = f2tf32(v);
        }
        // fill Bs (32xNC): coalesced over n
#pragma unroll
        for (int i = 0; i < (BK * NC) / 256; ++i) {
            int idx = tid + i * 256;
            int kk = idx / NC, n = idx % NC;
            int gk = k0 + kk;
            float v = (gk < K) ? B[gk * NC + n] : 0.f;
            Bs[kk][n] = f2tf32(v);
        }
        __syncthreads();

        int nk8 = min(4, (K - k0 + 7) >> 3);
        for (int kk8 = 0; kk8 < nk8; ++kk8) {
            int kb = kk8 * 8;
            uint32_t a0 = As[m0 + qr    ][kb + qc    ];
            uint32_t a1 = As[m0 + qr + 8][kb + qc    ];
            uint32_t a2 = As[m0 + qr    ][kb + qc + 4];
            uint32_t a3 = As[m0 + qr + 8][kb + qc + 4];
#pragma unroll
            for (int nt = 0; nt < NT; ++nt) {
                uint32_t b0 = Bs[kb + qc    ][nt * 8 + qr];
                uint32_t b1 = Bs[kb + qc + 4][nt * 8 + qr];
                asm volatile(
                    "mma.sync.aligned.m16n8k8.row.col.f32.tf32.tf32.f32 "
                    "{%0,%1,%2,%3}, {%4,%5,%6,%7}, {%8,%9}, {%0,%1,%2,%3};"
                    : "+f"(acc[nt][0]), "+f"(acc[nt][1]),
                      "+f"(acc[nt][2]), "+f"(acc[nt][3])
                    : "r"(a0), "r"(a1), "r"(a2), "r"(a3), "r"(b0), "r"(b1));
            }
        }
        __syncthreads();
    }

    // epilogue: c0/c1 -> (row, col..col+1), c2/c3 -> (row+8, ...)
    int gr0 = rowBase + m0 + qr;
    int gr1 = gr0 + 8;
#pragma unroll
    for (int nt = 0; nt < NT; ++nt) {
        int c = nt * 8 + 2 * qc;
        float b0v = (LAYER == 1) ? g_b1c[c]     : 0.f;
        float b1v = (LAYER == 1) ? g_b1c[c + 1] : 0.f;
        if (gr0 < M) {
            float2 v = make_float2(acc[nt][0] + b0v, acc[nt][1] + b1v);
            *reinterpret_cast<float2*>(&C[(size_t)gr0 * NC + c]) = v;
        }
        if (gr1 < M) {
            float2 v = make_float2(acc[nt][2] + b0v, acc[nt][3] + b1v);
            *reinterpret_cast<float2*>(&C[(size_t)gr1 * NC + c]) = v;
        }
    }
}

// ---------------- per-node attention coefficients ----------------
template<int NJ, int LAYER>
__global__ void alpha_kernel(const float* __restrict__ a_src,
                             const float* __restrict__ a_dst, int n) {
    constexpr int NC = 32 * NJ;
    const float* h  = (LAYER == 1) ? g_h1  : g_h2;
    float* out_s    = (LAYER == 1) ? g_as1 : g_as2;
    float* out_d    = (LAYER == 1) ? g_ad1 : g_ad2;
    int gw   = (blockIdx.x * blockDim.x + threadIdx.x) >> 5;
    int lane = threadIdx.x & 31;
    if (gw >= n) return;
    const float* hp = h + (size_t)gw * NC + lane * NJ;
    float ss = 0.f, sd = 0.f;
#pragma unroll
    for (int j = 0; j < NJ; ++j) {
        float v = hp[j];
        int c = lane * NJ + j;
        ss = fmaf(v, a_src[c], ss);
        sd = fmaf(v, a_dst[c], sd);
    }
#pragma unroll
    for (int off = 4; off; off >>= 1) {
        ss += __shfl_down_sync(0xffffffffu, ss, off, 8);
        sd += __shfl_down_sync(0xffffffffu, sd, off, 8);
    }
    if ((lane & 7) == 0) {
        out_s[gw * 4 + (lane >> 3)] = ss;
        out_d[gw * 4 + (lane >> 3)] = sd;
    }
}

// ---------------- fused edge pass: online segment-softmax + weighted gather ----------------
template<int NJ, int LAYER>
__global__ void agg_kernel(const float* __restrict__ bias,
                           float* __restrict__ outp, int n) {
    constexpr int NC = 32 * NJ;
    const float* h   = (LAYER == 1) ? g_h1  : g_h2;
    const float* asv = (LAYER == 1) ? g_as1 : g_as2;
    const float* adv = (LAYER == 1) ? g_ad1 : g_ad2;
    float* out       = (LAYER == 1) ? g_out1 : outp;
    int gw   = (blockIdx.x * blockDim.x + threadIdx.x) >> 5;
    int lane = threadIdx.x & 31;
    if (gw >= n) return;
    int myh  = lane & 3;
    int hidx = lane >> 3;

    float4 adq = *reinterpret_cast<const float4*>(adv + gw * 4);
    float ad_m = (myh == 0) ? adq.x : (myh == 1) ? adq.y : (myh == 2) ? adq.z : adq.w;

    float m = -1e30f, s = 0.f;
    float acc[NJ];
#pragma unroll
    for (int j = 0; j < NJ; ++j) acc[j] = 0.f;

    int e0 = g_rowp[gw], e1 = g_rowp[gw + 1];
    for (int k = e0; k < e1; ++k) {
        int src = g_colv[k];
        float4 aq = *reinterpret_cast<const float4*>(asv + src * 4);
        float av = (myh == 0) ? aq.x : (myh == 1) ? aq.y : (myh == 2) ? aq.z : aq.w;
        float e = av + ad_m;
        e = fmaxf(e, 0.2f * e);                 // LeakyReLU
        float nm = fmaxf(m, e);
        float fl = __expf(m - nm);
        float pl = __expf(e - nm);
        s = fmaf(s, fl, pl);
        m = nm;
        float fj = __shfl_sync(0xffffffffu, fl, hidx);
        float pj = __shfl_sync(0xffffffffu, pl, hidx);
        const float* hp = h + (size_t)src * NC + lane * NJ;
        if (NJ == 4) {
            float4 hv = *reinterpret_cast<const float4*>(hp);
            acc[0] = fmaf(pj, hv.x, acc[0] * fj);
            acc[1] = fmaf(pj, hv.y, acc[1] * fj);
            acc[2] = fmaf(pj, hv.z, acc[2] * fj);
            acc[3] = fmaf(pj, hv.w, acc[3] * fj);
        } else {
#pragma unroll
            for (int j = 0; j < NJ; ++j)
                acc[j] = fmaf(pj, hp[j], acc[j] * fj);
        }
    }
    float sj  = __shfl_sync(0xffffffffu, s, hidx);
    float inv = 1.0f / sj;
    float* op = out + (size_t)gw * NC + lane * NJ;
#pragma unroll
    for (int j = 0; j < NJ; ++j) {
        float v = acc[j] * inv + bias[lane * NJ + j];
        if (LAYER == 1) v = (v > 0.f) ? v : expm1f(v);   // ELU after layer 1
        op[j] = v;
    }
}

// ---------------- launch ----------------
extern "C" void kernel_launch(void* const* d_in, const int* in_sizes, int n_in,
                              void* d_out, int out_size) {
    const float* x      = (const float*)d_in[0];
    const void*  ei     = d_in[1];
    const float* gamma  = (const float*)d_in[2];
    const float* beta   = (const float*)d_in[3];
    const float* mean   = (const float*)d_in[4];
    const float* var    = (const float*)d_in[5];
    const float* W1     = (const float*)d_in[6];
    const float* a1_src = (const float*)d_in[7];
    const float* a1_dst = (const float*)d_in[8];
    const float* b1     = (const float*)d_in[9];
    const float* W2     = (const float*)d_in[10];
    const float* a2_src = (const float*)d_in[11];
    const float* a2_dst = (const float*)d_in[12];
    const float* b2     = (const float*)d_in[13];
    float*       out    = (float*)d_out;

    const int NWB = 6250;                 // warp-per-node kernels: 8 nodes/block
    const int EB  = (E_TOT + 255) / 256;
    const int GB  = (N_NODES + 127) / 128;

    // CSR build
    detect_kernel<<<1, 1>>>((const int*)ei);
    zero_kernel<<<SCAN_B, 256>>>();
    count_kernel<<<EB, 256>>>(ei);
    scan1_kernel<<<SCAN_B, 256>>>();
    scan2_kernel<<<1, 256>>>();
    scan3_kernel<<<SCAN_B, 256>>>();
    scatter_kernel<<<EB, 256>>>(ei);

    // BN fold + layer 1
    prep_w1_kernel<<<1, 128>>>(W1, gamma, beta, mean, var, b1);
    gemm_tc_kernel<1><<<GB, 256>>>(x, nullptr, N_NODES);
    alpha_kernel<4, 1><<<NWB, 256>>>(a1_src, a1_dst, N_NODES);
    agg_kernel<4, 1><<<NWB, 256>>>(b1, nullptr, N_NODES);

    // layer 2
    gemm_tc_kernel<2><<<GB, 256>>>(nullptr, W2, N_NODES);
    alpha_kernel<5, 2><<<NWB, 256>>>(a2_src, a2_dst, N_NODES);
    agg_kernel<5, 2><<<NWB, 256>>>(b2, out, N_NODES);
}

// round 5
// speedup vs baseline: 1.4296x; 1.0759x over previous
#include <cuda_runtime.h>
#include <cstdint>

#define N_NODES 50000
#define N_EDGES 800000
#define E_TOT   (N_EDGES + N_NODES)
#define IN_F    129
#define SCAN_B  ((N_NODES + 255) / 256)   // 196

// ---------------- scratch (static device globals; no allocation APIs) ----------------
__device__ __align__(16) float g_h1  [N_NODES * 128];
__device__ __align__(16) float g_out1[N_NODES * 128];
__device__ __align__(16) float g_h2  [N_NODES * 160];
__device__ __align__(16) float g_as1 [N_NODES * 4];
__device__ __align__(16) float g_ad1 [N_NODES * 4];
__device__ __align__(16) float g_as2 [N_NODES * 4];
__device__ __align__(16) float g_ad2 [N_NODES * 4];
__device__ __align__(16) float g_W1s [IN_F * 128];
__device__ __align__(16) float g_b1c [128];
__device__ int   g_deg [N_NODES];
__device__ int   g_cnt [N_NODES];
__device__ int   g_rowp[N_NODES + 1];
__device__ int   g_colv[E_TOT];
__device__ int   g_bsum[256];
__device__ int   g_is64;

// ---------------- edge_index dtype sniff ----------------
__global__ void detect_kernel(const int* __restrict__ ei32) {
    int ok = 1;
    for (int i = 1; i < 256; i += 2)
        if (ei32[i] != 0) ok = 0;
    g_is64 = ok;
}

__device__ __forceinline__ int edge_at(const void* ei, long long idx) {
    int v;
    if (g_is64) v = (int)((const long long*)ei)[idx];
    else        v = ((const int*)ei)[idx];
    v = v < 0 ? 0 : v;
    return v >= N_NODES ? N_NODES - 1 : v;
}

// ---------------- fold BatchNorm into W1 ----------------
__global__ void prep_w1_kernel(const float* __restrict__ W1,
                               const float* __restrict__ gamma,
                               const float* __restrict__ beta,
                               const float* __restrict__ mean,
                               const float* __restrict__ var,
                               const float* __restrict__ b1) {
    int c = threadIdx.x;           // 128 threads
    float acc = b1[c];
    for (int k = 0; k < IN_F; ++k) {
        float sc = gamma[k] * rsqrtf(var[k] + 1e-5f);
        float sh = beta[k] - mean[k] * sc;
        float w  = W1[k * 128 + c];
        g_W1s[k * 128 + c] = sc * w;
        acc += sh * w;
    }
    g_b1c[c] = acc;
}

// ---------------- CSR build (by destination) ----------------
__global__ void zero_kernel() {
    int i = blockIdx.x * blockDim.x + threadIdx.x;
    if (i < N_NODES) { g_deg[i] = 0; g_cnt[i] = 0; }
}

__global__ void count_kernel(const void* __restrict__ ei) {
    int e = blockIdx.x * blockDim.x + threadIdx.x;
    if (e >= E_TOT) return;
    int dst = (e < N_EDGES) ? edge_at(ei, (long long)N_EDGES + e) : (e - N_EDGES);
    atomicAdd(&g_deg[dst], 1);
}

__global__ void scan1_kernel() {                 // SCAN_B blocks x 256
    __shared__ int w[8];
    int i = blockIdx.x * 256 + threadIdx.x;
    int v = (i < N_NODES) ? g_deg[i] : 0;
#pragma unroll
    for (int off = 16; off; off >>= 1) v += __shfl_down_sync(0xffffffffu, v, off);
    if ((threadIdx.x & 31) == 0) w[threadIdx.x >> 5] = v;
    __syncthreads();
    if (threadIdx.x == 0) {
        int s = 0;
#pragma unroll
        for (int j = 0; j < 8; ++j) s += w[j];
        g_bsum[blockIdx.x] = s;
    }
}

__global__ void scan2_kernel() {                 // 1 block x 256
    __shared__ int sh[256];
    int t = threadIdx.x;
    int v = (t < SCAN_B) ? g_bsum[t] : 0;
    sh[t] = v;
    __syncthreads();
    for (int off = 1; off < 256; off <<= 1) {
        int u = (t >= off) ? sh[t - off] : 0;
        __syncthreads();
        sh[t] += u;
        __syncthreads();
    }
    if (t < SCAN_B) g_bsum[t] = sh[t] - v;       // exclusive block offset
    if (t == 0) g_rowp[N_NODES] = E_TOT;
}

__global__ void scan3_kernel() {                 // SCAN_B blocks x 256
    __shared__ int wsum[8];
    int t = threadIdx.x, lane = t & 31, w = t >> 5;
    int i = blockIdx.x * 256 + t;
    int v = (i < N_NODES) ? g_deg[i] : 0;
    int inc = v;
#pragma unroll
    for (int off = 1; off < 32; off <<= 1) {
        int u = __shfl_up_sync(0xffffffffu, inc, off);
        if (lane >= off) inc += u;
    }
    if (lane == 31) wsum[w] = inc;
    __syncthreads();
    if (t == 0) {
        int r = 0;
#pragma unroll
        for (int j = 0; j < 8; ++j) { int x = wsum[j]; wsum[j] = r; r += x; }
    }
    __syncthreads();
    if (i < N_NODES) g_rowp[i] = g_bsum[blockIdx.x] + wsum[w] + inc - v;
}

__global__ void scatter_kernel(const void* __restrict__ ei) {
    int e = blockIdx.x * blockDim.x + threadIdx.x;
    if (e >= E_TOT) return;
    int src, dst;
    if (e < N_EDGES) {
        src = edge_at(ei, e);
        dst = edge_at(ei, (long long)N_EDGES + e);
    } else {
        src = dst = e - N_EDGES;
    }
    int pos = g_rowp[dst] + atomicAdd(&g_cnt[dst], 1);
    if (pos < E_TOT) g_colv[pos] = src;
}

// ---------------- TF32 tensor-core GEMM + fused alpha epilogue ----------------
__device__ __forceinline__ uint32_t f2tf32(float v) {
    uint32_t r;
    asm("cvt.rna.tf32.f32 %0, %1;" : "=r"(r) : "f"(v));
    return r;
}

template<int LAYER>
__global__ __launch_bounds__(256) void gemm_tc_kernel(const float* __restrict__ Ap,
                                                      const float* __restrict__ Bp,
                                                      const float* __restrict__ a_src,
                                                      const float* __restrict__ a_dst,
                                                      int M) {
    constexpr int NC  = (LAYER == 1) ? 128 : 160;
    constexpr int K   = (LAYER == 1) ? IN_F : 128;
    constexpr int LDA = (LAYER == 1) ? IN_F : 128;
    constexpr int BK  = 32;
    constexpr int NT  = NC / 8;
    const float* A = (LAYER == 1) ? Ap    : g_out1;
    const float* B = (LAYER == 1) ? g_W1s : Bp;
    float*       C = (LAYER == 1) ? g_h1  : g_h2;
    float*   out_s = (LAYER == 1) ? g_as1 : g_as2;
    float*   out_d = (LAYER == 1) ? g_ad1 : g_ad2;

    __shared__ uint32_t As[128][BK + 4];
    __shared__ uint32_t Bs[BK][NC + 8];

    int tid  = threadIdx.x;
    int lane = tid & 31;
    int m0   = (tid >> 5) * 16;
    int qr   = lane >> 2, qc = lane & 3;
    int rowBase = blockIdx.x * 128;

    float acc[NT][4];
#pragma unroll
    for (int nt = 0; nt < NT; ++nt)
#pragma unroll
        for (int j = 0; j < 4; ++j) acc[nt][j] = 0.f;

    for (int k0 = 0; k0 < K; k0 += BK) {
#pragma unroll
        for (int i = 0; i < 16; ++i) {
            int idx = tid + i * 256;
            int r = idx >> 5, kk = idx & 31;
            int gr = rowBase + r, gk = k0 + kk;
            float v = (gr < M && gk < K) ? A[(size_t)gr * LDA + gk] : 0.f;
            As[r][kk] = f2tf32(v);
        }
#pragma unroll
        for (int i = 0; i < (BK * NC) / 256; ++i) {
            int idx = tid + i * 256;
            int kk = idx / NC, n = idx % NC;
            int gk = k0 + kk;
            float v = (gk < K) ? B[gk * NC + n] : 0.f;
            Bs[kk][n] = f2tf32(v);
        }
        __syncthreads();

        int nk8 = min(4, (K - k0 + 7) >> 3);
        for (int kk8 = 0; kk8 < nk8; ++kk8) {
            int kb = kk8 * 8;
            uint32_t a0 = As[m0 + qr    ][kb + qc    ];
            uint32_t a1 = As[m0 + qr + 8][kb + qc    ];
            uint32_t a2 = As[m0 + qr    ][kb + qc + 4];
            uint32_t a3 = As[m0 + qr + 8][kb + qc + 4];
#pragma unroll
            for (int nt = 0; nt < NT; ++nt) {
                uint32_t b0 = Bs[kb + qc    ][nt * 8 + qr];
                uint32_t b1 = Bs[kb + qc + 4][nt * 8 + qr];
                asm volatile(
                    "mma.sync.aligned.m16n8k8.row.col.f32.tf32.tf32.f32 "
                    "{%0,%1,%2,%3}, {%4,%5,%6,%7}, {%8,%9}, {%0,%1,%2,%3};"
                    : "+f"(acc[nt][0]), "+f"(acc[nt][1]),
                      "+f"(acc[nt][2]), "+f"(acc[nt][3])
                    : "r"(a0), "r"(a1), "r"(a2), "r"(a3), "r"(b0), "r"(b1));
            }
        }
        __syncthreads();
    }

    // ---- epilogue: store h, accumulate per-head alpha partials ----
    int gr0 = rowBase + m0 + qr;
    int gr1 = gr0 + 8;
    float ss0[4] = {0,0,0,0}, ss1[4] = {0,0,0,0};
    float dd0[4] = {0,0,0,0}, dd1[4] = {0,0,0,0};
#pragma unroll
    for (int nt = 0; nt < NT; ++nt) {
        int c  = nt * 8 + 2 * qc;
        int hd = (LAYER == 1) ? (nt >> 2) : (nt / 5);
        float b0v = (LAYER == 1) ? g_b1c[c]     : 0.f;
        float b1v = (LAYER == 1) ? g_b1c[c + 1] : 0.f;
        float v00 = acc[nt][0] + b0v, v01 = acc[nt][1] + b1v;
        float v10 = acc[nt][2] + b0v, v11 = acc[nt][3] + b1v;
        if (gr0 < M)
            *reinterpret_cast<float2*>(&C[(size_t)gr0 * NC + c]) = make_float2(v00, v01);
        if (gr1 < M)
            *reinterpret_cast<float2*>(&C[(size_t)gr1 * NC + c]) = make_float2(v10, v11);
        float as0 = a_src[c], as1v = a_src[c + 1];
        float ad0 = a_dst[c], ad1v = a_dst[c + 1];
        ss0[hd] = fmaf(v00, as0, fmaf(v01, as1v, ss0[hd]));
        ss1[hd] = fmaf(v10, as0, fmaf(v11, as1v, ss1[hd]));
        dd0[hd] = fmaf(v00, ad0, fmaf(v01, ad1v, dd0[hd]));
        dd1[hd] = fmaf(v10, ad0, fmaf(v11, ad1v, dd1[hd]));
    }
#pragma unroll
    for (int h = 0; h < 4; ++h) {
#pragma unroll
        for (int off = 2; off; off >>= 1) {
            ss0[h] += __shfl_down_sync(0xffffffffu, ss0[h], off, 4);
            ss1[h] += __shfl_down_sync(0xffffffffu, ss1[h], off, 4);
            dd0[h] += __shfl_down_sync(0xffffffffu, dd0[h], off, 4);
            dd1[h] += __shfl_down_sync(0xffffffffu, dd1[h], off, 4);
        }
    }
    if (qc == 0) {
        if (gr0 < M) {
#pragma unroll
            for (int h = 0; h < 4; ++h) {
                out_s[gr0 * 4 + h] = ss0[h];
                out_d[gr0 * 4 + h] = dd0[h];
            }
        }
        if (gr1 < M) {
#pragma unroll
            for (int h = 0; h < 4; ++h) {
                out_s[gr1 * 4 + h] = ss1[h];
                out_d[gr1 * 4 + h] = dd1[h];
            }
        }
    }
}

// ---------------- layer-1 edge pass: two-pass segment softmax, shuffle-free ----------------
// One warp per dst node; lane owns channels c = 4*lane..4*lane+3, head = lane>>3.
__global__ void agg1_kernel(const float* __restrict__ bias, int n) {
    int gw   = (blockIdx.x * blockDim.x + threadIdx.x) >> 5;
    int lane = threadIdx.x & 31;
    if (gw >= n) return;
    int hidx = lane >> 3;
    float ad = g_ad1[gw * 4 + hidx];
    int e0 = g_rowp[gw], e1 = g_rowp[gw + 1];

    float m = -1e30f;
    for (int k = e0; k < e1; ++k) {
        int src = g_colv[k];
        float e = g_as1[src * 4 + hidx] + ad;
        e = fmaxf(e, 0.2f * e);
        m = fmaxf(m, e);
    }
    float s = 0.f, a0 = 0.f, a1 = 0.f, a2 = 0.f, a3 = 0.f;
    const float4* h4 = reinterpret_cast<const float4*>(g_h1);
    for (int k = e0; k < e1; ++k) {
        int src = g_colv[k];
        float e = g_as1[src * 4 + hidx] + ad;
        e = fmaxf(e, 0.2f * e);
        float p = __expf(e - m);
        s += p;
        float4 hv = h4[src * 32 + lane];
        a0 = fmaf(p, hv.x, a0);
        a1 = fmaf(p, hv.y, a1);
        a2 = fmaf(p, hv.z, a2);
        a3 = fmaf(p, hv.w, a3);
    }
    float inv = 1.0f / s;
    float4 bv = reinterpret_cast<const float4*>(bias)[lane];
    float v0 = a0 * inv + bv.x;
    float v1 = a1 * inv + bv.y;
    float v2 = a2 * inv + bv.z;
    float v3 = a3 * inv + bv.w;
    v0 = (v0 > 0.f) ? v0 : expm1f(v0);
    v1 = (v1 > 0.f) ? v1 : expm1f(v1);
    v2 = (v2 > 0.f) ? v2 : expm1f(v2);
    v3 = (v3 > 0.f) ? v3 : expm1f(v3);
    reinterpret_cast<float4*>(g_out1)[gw * 32 + lane] = make_float4(v0, v1, v2, v3);
}

// ---------------- layer-2 edge pass ----------------
// lane owns c1 = 4*lane (head lane/10); lanes 0-7 also own c2 = 128+4*lane (head (32+lane)/10).
__global__ void agg2_kernel(const float* __restrict__ bias,
                            float* __restrict__ out, int n) {
    int gw   = (blockIdx.x * blockDim.x + threadIdx.x) >> 5;
    int lane = threadIdx.x & 31;
    if (gw >= n) return;
    bool lo  = lane < 8;
    int h1i  = lane / 10;
    int h2i  = lo ? (32 + lane) / 10 : 3;
    float ad1 = g_ad2[gw * 4 + h1i];
    float ad2 = g_ad2[gw * 4 + h2i];
    int e0 = g_rowp[gw], e1 = g_rowp[gw + 1];

    float m1 = -1e30f, m2 = -1e30f;
    for (int k = e0; k < e1; ++k) {
        int src = g_colv[k];
        float ea = g_as2[src * 4 + h1i] + ad1;
        float eb = g_as2[src * 4 + h2i] + ad2;
        ea = fmaxf(ea, 0.2f * ea);
        eb = fmaxf(eb, 0.2f * eb);
        m1 = fmaxf(m1, ea);
        m2 = fmaxf(m2, eb);
    }
    float s1 = 0.f, s2 = 0.f;
    float a0 = 0.f, a1 = 0.f, a2 = 0.f, a3 = 0.f;
    float b0 = 0.f, b1 = 0.f, b2 = 0.f, b3 = 0.f;
    const float4* h4 = reinterpret_cast<const float4*>(g_h2);
    for (int k = e0; k < e1; ++k) {
        int src = g_colv[k];
        float ea = g_as2[src * 4 + h1i] + ad1;
        float eb = g_as2[src * 4 + h2i] + ad2;
        ea = fmaxf(ea, 0.2f * ea);
        eb = fmaxf(eb, 0.2f * eb);
        float p1 = __expf(ea - m1);
        float p2 = __expf(eb - m2);
        s1 += p1; s2 += p2;
        float4 hv = h4[src * 40 + lane];
        a0 = fmaf(p1, hv.x, a0);
        a1 = fmaf(p1, hv.y, a1);
        a2 = fmaf(p1, hv.z, a2);
        a3 = fmaf(p1, hv.w, a3);
        if (lo) {
            float4 hw = h4[src * 40 + 32 + lane];
            b0 = fmaf(p2, hw.x, b0);
            b1 = fmaf(p2, hw.y, b1);
            b2 = fmaf(p2, hw.z, b2);
            b3 = fmaf(p2, hw.w, b3);
        }
    }
    float inv1 = 1.0f / s1;
    float4 bv = reinterpret_cast<const float4*>(bias)[lane];
    reinterpret_cast<float4*>(out)[(size_t)gw * 40 + lane] =
        make_float4(a0 * inv1 + bv.x, a1 * inv1 + bv.y,
                    a2 * inv1 + bv.z, a3 * inv1 + bv.w);
    if (lo) {
        float inv2 = 1.0f / s2;
        float4 bw = reinterpret_cast<const float4*>(bias)[32 + lane];
        reinterpret_cast<float4*>(out)[(size_t)gw * 40 + 32 + lane] =
            make_float4(b0 * inv2 + bw.x, b1 * inv2 + bw.y,
                        b2 * inv2 + bw.z, b3 * inv2 + bw.w);
    }
}

// ---------------- launch ----------------
extern "C" void kernel_launch(void* const* d_in, const int* in_sizes, int n_in,
                              void* d_out, int out_size) {
    const float* x      = (const float*)d_in[0];
    const void*  ei     = d_in[1];
    const float* gamma  = (const float*)d_in[2];
    const float* beta   = (const float*)d_in[3];
    const float* mean   = (const float*)d_in[4];
    const float* var    = (const float*)d_in[5];
    const float* W1     = (const float*)d_in[6];
    const float* a1_src = (const float*)d_in[7];
    const float* a1_dst = (const float*)d_in[8];
    const float* b1     = (const float*)d_in[9];
    const float* W2     = (const float*)d_in[10];
    const float* a2_src = (const float*)d_in[11];
    const float* a2_dst = (const float*)d_in[12];
    const float* b2     = (const float*)d_in[13];
    float*       out    = (float*)d_out;

    const int NWB = 6250;                 // warp-per-node kernels: 8 nodes/block
    const int EB  = (E_TOT + 255) / 256;
    const int GB  = (N_NODES + 127) / 128;

    // CSR build
    detect_kernel<<<1, 1>>>((const int*)ei);
    zero_kernel<<<SCAN_B, 256>>>();
    count_kernel<<<EB, 256>>>(ei);
    scan1_kernel<<<SCAN_B, 256>>>();
    scan2_kernel<<<1, 256>>>();
    scan3_kernel<<<SCAN_B, 256>>>();
    scatter_kernel<<<EB, 256>>>(ei);

    // BN fold + layer 1 (GEMM fuses alpha computation)
    prep_w1_kernel<<<1, 128>>>(W1, gamma, beta, mean, var, b1);
    gemm_tc_kernel<1><<<GB, 256>>>(x, nullptr, a1_src, a1_dst, N_NODES);
    agg1_kernel<<<NWB, 256>>>(b1, N_NODES);

    // layer 2
    gemm_tc_kernel<2><<<GB, 256>>>(nullptr, W2, a2_src, a2_dst, N_NODES);
    agg2_kernel<<<NWB, 256>>>(b2, out, N_NODES);
}